// round 15
// baseline (speedup 1.0000x reference)
#include <cuda_runtime.h>
#include <cuda_bf16.h>
#include <cstdint>
#include <cstddef>

#define Bn   64
#define Tn   1024
#define Dn   512
#define Hn   256
#define Gn   1024     /* 4*H */
#define NTOT 2048     /* both directions */
#define Mrows (Bn * Tn)
#define EPSC 0.001f

// ---------------- scratch (static device globals; allocation-free) ----------------
__device__ float          g_xg[(size_t)Bn * Tn * NTOT];   // 512 MB  xg for both dirs
__device__ __nv_bfloat16  g_ahi[(size_t)Mrows * Dn];      // 64 MB
__device__ __nv_bfloat16  g_alo[(size_t)Mrows * Dn];      // 64 MB
__device__ __nv_bfloat16  g_wthi[(size_t)NTOT * Dn];      // 2 MB  W^T hi  [n][k]
__device__ __nv_bfloat16  g_wtlo[(size_t)NTOT * Dn];      // 2 MB  W^T lo
__device__ float          g_bias2[NTOT];
__device__ float          g_hbuf[2][2][Bn * Hn];          // [parity][dir][b*H+j]
__device__ int            g_len[Bn];
__device__ unsigned       g_flags[128];                   // [dir*64 + bs*8 + hs]

__device__ __forceinline__ float sigf(float x)  { return 1.0f / (1.0f + __expf(-x)); }
__device__ __forceinline__ float tanhf_(float x){ return 2.0f / (1.0f + __expf(-2.0f * x)) - 1.0f; }

__device__ __forceinline__ uint32_t smem_u32(const void* p) {
    uint32_t a;
    asm("{ .reg .u64 t; cvta.to.shared.u64 t, %1; cvt.u32.u64 %0, t; }" : "=r"(a) : "l"(p));
    return a;
}
__device__ __forceinline__ void cp16(uint32_t dst, const void* src) {
    asm volatile("cp.async.cg.shared.global [%0], [%1], 16;" :: "r"(dst), "l"(src));
}
#define CP_COMMIT() asm volatile("cp.async.commit_group;" ::: "memory")
#define CP_WAIT2()  asm volatile("cp.async.wait_group 2;" ::: "memory")
#define CP_WAIT1()  asm volatile("cp.async.wait_group 1;" ::: "memory")
#define CP_WAIT0()  asm volatile("cp.async.wait_group 0;" ::: "memory")

__device__ __forceinline__ void ldsm4(uint32_t& r0, uint32_t& r1, uint32_t& r2, uint32_t& r3,
                                      uint32_t addr) {
    asm volatile("ldmatrix.sync.aligned.m8n8.x4.shared.b16 {%0,%1,%2,%3}, [%4];"
                 : "=r"(r0), "=r"(r1), "=r"(r2), "=r"(r3) : "r"(addr));
}
__device__ __forceinline__ void mma16816(float* c, const uint32_t* a, uint32_t b0, uint32_t b1) {
    asm volatile("mma.sync.aligned.m16n8k16.row.col.f32.bf16.bf16.f32 "
                 "{%0,%1,%2,%3}, {%4,%5,%6,%7}, {%8,%9}, {%0,%1,%2,%3};"
                 : "+f"(c[0]), "+f"(c[1]), "+f"(c[2]), "+f"(c[3])
                 : "r"(a[0]), "r"(a[1]), "r"(a[2]), "r"(a[3]), "r"(b0), "r"(b1));
}
__device__ __forceinline__ uint32_t pack_bf16(float x, float y) {
    __nv_bfloat162 v = {__float2bfloat16(x), __float2bfloat16(y)};
    return *reinterpret_cast<uint32_t*>(&v);
}

// ---------------- init: zero the step-barrier flags (runs every graph replay) ------
__global__ void init_kernel() {
    if (threadIdx.x < 128) g_flags[threadIdx.x] = 0u;
}

// ---------------- lengths ----------------------------------------------------------
__global__ void lengths_kernel(const float* __restrict__ pads) {
    __shared__ float red[256];
    const int b = blockIdx.x;
    float s = 0.f;
    for (int t = threadIdx.x; t < Tn; t += 256) s += pads[b * Tn + t];
    red[threadIdx.x] = s;
    __syncthreads();
    for (int o = 128; o > 0; o >>= 1) {
        if (threadIdx.x < o) red[threadIdx.x] += red[threadIdx.x + o];
        __syncthreads();
    }
    if (threadIdx.x == 0) g_len[b] = Tn - (int)(red[0] + 0.5f);
}

// ---------------- BN + mask + bf16 hi/lo split -------------------------------------
__global__ void bn_split_kernel(const float* __restrict__ in, const float* __restrict__ pads,
                                const float* __restrict__ scale, const float* __restrict__ bias,
                                const float* __restrict__ mean, const float* __restrict__ var) {
    const int row = blockIdx.x;
    const int d   = threadIdx.x * 4;
    const float keep = 1.0f - pads[row];
    float4 v  = *(const float4*)(in + (size_t)row * Dn + d);
    float4 sc = *(const float4*)(scale + d);
    float4 bi = *(const float4*)(bias + d);
    float4 mu = *(const float4*)(mean + d);
    float4 va = *(const float4*)(var + d);
    float o[4];
    o[0] = ((v.x - mu.x) * ((1.0f + sc.x) * rsqrtf(va.x + EPSC)) + bi.x) * keep;
    o[1] = ((v.y - mu.y) * ((1.0f + sc.y) * rsqrtf(va.y + EPSC)) + bi.y) * keep;
    o[2] = ((v.z - mu.z) * ((1.0f + sc.z) * rsqrtf(va.z + EPSC)) + bi.z) * keep;
    o[3] = ((v.w - mu.w) * ((1.0f + sc.w) * rsqrtf(va.w + EPSC)) + bi.w) * keep;
    __nv_bfloat16 hi[4], lo[4];
#pragma unroll
    for (int q = 0; q < 4; q++) {
        hi[q] = __float2bfloat16(o[q]);
        lo[q] = __float2bfloat16(o[q] - __bfloat162float(hi[q]));
    }
    *(__nv_bfloat162*)(g_ahi + (size_t)row * Dn + d)     = {hi[0], hi[1]};
    *(__nv_bfloat162*)(g_ahi + (size_t)row * Dn + d + 2) = {hi[2], hi[3]};
    *(__nv_bfloat162*)(g_alo + (size_t)row * Dn + d)     = {lo[0], lo[1]};
    *(__nv_bfloat162*)(g_alo + (size_t)row * Dn + d + 2) = {lo[2], lo[3]};
}

// ---------------- W transpose + split + bias concat --------------------------------
__global__ void wprep_kernel(const float* __restrict__ Wxf, const float* __restrict__ Wxb,
                             const float* __restrict__ bf, const float* __restrict__ bb) {
    const int n = blockIdx.x;                 // 0..2047
    const float* W = (n < Gn) ? Wxf : Wxb;
    const int nl = n & (Gn - 1);
    for (int k = threadIdx.x; k < Dn; k += 128) {
        float v = W[(size_t)k * Gn + nl];
        __nv_bfloat16 h = __float2bfloat16(v);
        g_wthi[(size_t)n * Dn + k] = h;
        g_wtlo[(size_t)n * Dn + k] = __float2bfloat16(v - __bfloat162float(h));
    }
    if (threadIdx.x == 0) g_bias2[n] = (n < Gn) ? bf[nl] : bb[nl];
}

// ---------------- mma.sync GEMM, pad-row skip, 3-stage cp.async pipeline -----------
#define GCHUNKS 24
#define GSTAGE 32768
#define GSMEM  (3 * GSTAGE)

__global__ void __launch_bounds__(256, 2) gemm_mma_kernel() {
    const int n0 = blockIdx.x * 128;
    const int m0 = blockIdx.y * 128;

    {   // pad-block skip: entire block is padding -> xg never read, exit
        const int b  = m0 >> 10;
        const int t0 = m0 & (Tn - 1);
        if (t0 >= g_len[b]) return;
    }

    extern __shared__ __align__(1024) char sm[];
    const uint32_t smb = smem_u32(sm);
    const int tid  = threadIdx.x;
    const int wid  = tid >> 5, lane = tid & 31;
    const int wm   = wid & 3;
    const int wn   = wid >> 2;

    uint32_t sdstA[4];
    int arow[4];
#pragma unroll
    for (int j = 0; j < 4; j++) {
        const int item = tid + j * 256;
        const int row = item >> 3, ci = item & 7;
        arow[j] = row;
        sdstA[j] = row * 128 + ((ci * 16) ^ ((row & 7) << 4));
    }

    auto load_chunk = [&](int c, int s) {
        const int r  = c >> 3;
        const int kp = (c & 7) * 64;
        const __nv_bfloat16* Asrc = (r == 1) ? g_alo : g_ahi;
        const __nv_bfloat16* Bsrc = (r == 2) ? g_wtlo : g_wthi;
        const uint32_t aB = smb + s * GSTAGE;
        const uint32_t bB = aB + 16384;
#pragma unroll
        for (int j = 0; j < 4; j++) {
            const int item = tid + j * 256;
            const int ci = item & 7;
            cp16(aB + sdstA[j], Asrc + (size_t)(m0 + arow[j]) * Dn + kp + ci * 8);
        }
#pragma unroll
        for (int j = 0; j < 4; j++) {
            const int item = tid + j * 256;
            const int ci = item & 7;
            cp16(bB + sdstA[j], Bsrc + (size_t)(n0 + arow[j]) * Dn + kp + ci * 8);
        }
    };

    uint32_t aRel[2], aSx[2];
#pragma unroll
    for (int f = 0; f < 2; f++) {
        const int row = wm * 32 + f * 16 + (lane & 15);
        aRel[f] = row * 128;
        aSx[f]  = (row & 7) << 4;
    }
    uint32_t bRel[4], bSx[4];
#pragma unroll
    for (int q = 0; q < 4; q++) {
        const int row = wn * 64 + q * 16 + (lane & 15);
        bRel[q] = row * 128;
        bSx[q]  = (row & 7) << 4;
    }
    const uint32_t halfOff = (lane >> 4) * 16;

    float acc[2][8][4];
#pragma unroll
    for (int i = 0; i < 2; i++)
#pragma unroll
        for (int j = 0; j < 8; j++)
#pragma unroll
            for (int q = 0; q < 4; q++) acc[i][j][q] = 0.f;

    load_chunk(0, 0); CP_COMMIT();
    load_chunk(1, 1); CP_COMMIT();
    load_chunk(2, 2); CP_COMMIT();

    for (int i = 0; i < GCHUNKS; i++) {
        const int buf = i % 3;
        if (i < GCHUNKS - 2)      { CP_WAIT2(); }
        else if (i == GCHUNKS - 2){ CP_WAIT1(); }
        else                      { CP_WAIT0(); }
        __syncthreads();

        const uint32_t aB = smb + buf * GSTAGE;
        const uint32_t bB = aB + 16384;
#pragma unroll
        for (int k16 = 0; k16 < 4; k16++) {
            const uint32_t kb = k16 * 32 + halfOff;
            uint32_t af[2][4];
#pragma unroll
            for (int f = 0; f < 2; f++)
                ldsm4(af[f][0], af[f][1], af[f][2], af[f][3], aB + aRel[f] + (kb ^ aSx[f]));
#pragma unroll
            for (int q = 0; q < 4; q++) {
                uint32_t r0, r1, r2, r3;
                ldsm4(r0, r1, r2, r3, bB + bRel[q] + (kb ^ bSx[q]));
#pragma unroll
                for (int f = 0; f < 2; f++) {
                    mma16816(acc[f][2 * q + 0], af[f], r0, r2);
                    mma16816(acc[f][2 * q + 1], af[f], r1, r3);
                }
            }
        }
        __syncthreads();
        if (i + 3 < GCHUNKS) { load_chunk(i + 3, buf); CP_COMMIT(); }
    }

#pragma unroll
    for (int f = 0; f < 2; f++) {
        const int r0 = m0 + wm * 32 + f * 16 + (lane >> 2);
#pragma unroll
        for (int nf = 0; nf < 8; nf++) {
            const int col = n0 + wn * 64 + nf * 8 + (lane & 3) * 2;
            const float2 bv = *(const float2*)(g_bias2 + col);
            float2 o0 = {acc[f][nf][0] + bv.x, acc[f][nf][1] + bv.y};
            float2 o1 = {acc[f][nf][2] + bv.x, acc[f][nf][3] + bv.y};
            *(float2*)(g_xg + (size_t)r0 * NTOT + col)       = o0;
            *(float2*)(g_xg + (size_t)(r0 + 8) * NTOT + col) = o1;
        }
    }
}

// ---------------- Recurrence: tensor-core dot, 3 independent accumulator chains ----
// gates[128c][8b] = Wslice[c][k] @ h[b][k]^T via mma m16n8k16 (A=W m=128, B=h n=8).
// Split terms accumulate into SEPARATE register quads (acc1/acc2/acc3) so the 48
// mma form 3 interleaved 16-deep chains instead of one 48-deep chain.
#define RSTR    264                       /* bf16 elems per smem row (528 B) */
#define OFF_WHH 0
#define OFF_WHL 67584                     /* 128*528 */
#define OFF_HHH 135168
#define OFF_HHL 143616                    /* +16*528 */
#define OFF_G   152064
#define OFF_C   156288                    /* +8*132*4 */
#define OFF_LEN 157312                    /* +256*4 */
#define REC_SMEM 157376

__global__ void __launch_bounds__(256, 1) recurrence_kernel(const float* __restrict__ Whf,
                                                            const float* __restrict__ Whb,
                                                            float* __restrict__ out) {
    extern __shared__ __align__(16) char smr[];
    const uint32_t smb = smem_u32(smr);
    __nv_bfloat16* Whh = (__nv_bfloat16*)(smr + OFF_WHH);
    __nv_bfloat16* Whl = (__nv_bfloat16*)(smr + OFF_WHL);
    float* g_sm  = (float*)(smr + OFF_G);     // [8][132]
    float* c_sm  = (float*)(smr + OFF_C);     // [256]
    int*   len_s = (int*)(smr + OFF_LEN);     // [8]

    const int tid = threadIdx.x;
    const int bx  = blockIdx.x;
    const int dir = bx >> 6;
    const int hs  = bx & 7;
    const int bs  = (bx >> 3) & 7;
    const int j0  = hs * 32;
    const int b0  = bs * 8;
    const float* Wh = dir ? Whb : Whf;

    // ---- init: W slice hi/lo into [c][k] layout (row = local col c = gate*32+jj)
    for (int idx = tid; idx < 32768; idx += 256) {
        const int n = idx & 127, k = idx >> 7;
        const int gate = n >> 5, jj = n & 31;
        const float v = Wh[(size_t)k * Gn + gate * Hn + j0 + jj];
        const __nv_bfloat16 h = __float2bfloat16(v);
        Whh[n * RSTR + k] = h;
        Whl[n * RSTR + k] = __float2bfloat16(v - __bfloat162float(h));
    }
    // zero both h tiles fully (incl. pad rows 8..15)
    for (int idx = tid; idx < (2 * 16 * RSTR * 2) / 4; idx += 256)
        ((uint32_t*)(smr + OFF_HHH))[idx] = 0;
    if (tid < 8) len_s[tid] = g_len[b0 + tid];
    c_sm[tid] = 0.f;
    __syncthreads();

    const int wid = tid >> 5, lane = tid & 31;
    // ldsm base addresses (k-dependent ks*32 added per step)
    const uint32_t aoff = (uint32_t)((wid * 16 + (lane & 15)) * 528 + (lane >> 4) * 16);
    const uint32_t aHH = smb + OFF_WHH + aoff;
    const uint32_t aHL = smb + OFF_WHL + aoff;
    const uint32_t boff = (uint32_t)((lane & 15) * 528 + (lane >> 4) * 16);
    const uint32_t bHH = smb + OFF_HHH + boff;
    const uint32_t bHL = smb + OFF_HHL + boff;

    // epilogue / xg mapping
    const int c_row = wid * 16 + (lane >> 2);            // local col, +8 sibling
    const int bA = (lane & 3) * 2, bB_ = bA + 1;         // two batches
    const int gcol0 = (c_row >> 5) * Hn + j0 + (c_row & 31);
    const int gcol1 = gcol0 + 8;
    const float* xg_dir = g_xg + dir * Gn;
    const float bias0 = g_bias2[dir * Gn + gcol0];       // pad-row substitute (exact)
    const float bias1 = g_bias2[dir * Gn + gcol1];
    const int lenA = len_s[bA], lenB = len_s[bB_];

    // conversion mapping
    const int cb = tid >> 5, ck = tid & 31;              // batch, k-octet
    const uint32_t cdstH = (uint32_t)(cb * 528 + ck * 16);

    // cell mapping
    const int ub = tid >> 5, uj = tid & 31;

    unsigned* myflag = &g_flags[dir * 64 + bs * 8 + hs];

    for (int t = 0; t < Tn; t++) {
        // ---- xg for this step: valid rows from memory, pad rows = bias (exact)
        const int rA = dir ? ((Tn - 1 - t + lenA) & (Tn - 1)) : t;
        const int rB = dir ? ((Tn - 1 - t + lenB) & (Tn - 1)) : t;
        const bool vA = rA < lenA, vB = rB < lenB;
        const float x00 = vA ? __ldg(xg_dir + ((size_t)(b0 + bA)  * Tn + rA) * NTOT + gcol0) : bias0;
        const float x01 = vB ? __ldg(xg_dir + ((size_t)(b0 + bB_) * Tn + rB) * NTOT + gcol0) : bias0;
        const float x10 = vA ? __ldg(xg_dir + ((size_t)(b0 + bA)  * Tn + rA) * NTOT + gcol1) : bias1;
        const float x11 = vB ? __ldg(xg_dir + ((size_t)(b0 + bB_) * Tn + rB) * NTOT + gcol1) : bias1;

        if (t > 0) {
            if (tid < 8) {
                const unsigned* fp = &g_flags[dir * 64 + bs * 8 + tid];
                unsigned v;
                do {
                    asm volatile("ld.acquire.gpu.u32 %0, [%1];" : "=r"(v) : "l"(fp) : "memory");
                } while (v < (unsigned)t);
            }
            __syncthreads();
            // h -> bf16 hi/lo tiles (rows 0..7)
            const float* hg = &g_hbuf[(t + 1) & 1][dir][0];
            const float4 h0 = __ldcg((const float4*)(hg + (size_t)(b0 + cb) * Hn + ck * 8));
            const float4 h1 = __ldcg((const float4*)(hg + (size_t)(b0 + cb) * Hn + ck * 8 + 4));
            const uint32_t p0 = pack_bf16(h0.x, h0.y), p1 = pack_bf16(h0.z, h0.w);
            const uint32_t p2 = pack_bf16(h1.x, h1.y), p3 = pack_bf16(h1.z, h1.w);
            const __nv_bfloat162* hp;
            hp = (const __nv_bfloat162*)&p0;
            const float l0 = h0.x - __bfloat162float(hp->x), l1 = h0.y - __bfloat162float(hp->y);
            hp = (const __nv_bfloat162*)&p1;
            const float l2 = h0.z - __bfloat162float(hp->x), l3 = h0.w - __bfloat162float(hp->y);
            hp = (const __nv_bfloat162*)&p2;
            const float l4 = h1.x - __bfloat162float(hp->x), l5 = h1.y - __bfloat162float(hp->y);
            hp = (const __nv_bfloat162*)&p3;
            const float l6 = h1.z - __bfloat162float(hp->x), l7 = h1.w - __bfloat162float(hp->y);
            *(uint4*)(smr + OFF_HHH + cdstH) = make_uint4(p0, p1, p2, p3);
            *(uint4*)(smr + OFF_HHL + cdstH) =
                make_uint4(pack_bf16(l0, l1), pack_bf16(l2, l3),
                           pack_bf16(l4, l5), pack_bf16(l6, l7));
            __syncthreads();
        }

        // ---- tensor dot: 3 independent accumulator chains (16 deep each)
        float acc1[4] = {0.f, 0.f, 0.f, 0.f};
        float acc2[4] = {0.f, 0.f, 0.f, 0.f};
        float acc3[4] = {0.f, 0.f, 0.f, 0.f};
#pragma unroll
        for (int ks = 0; ks < 16; ks++) {
            const uint32_t ko = ks * 32;
            uint32_t awh[4], awl[4], bh0, bh1, bh2, bh3, bl0, bl1, bl2, bl3;
            ldsm4(awh[0], awh[1], awh[2], awh[3], aHH + ko);
            ldsm4(awl[0], awl[1], awl[2], awl[3], aHL + ko);
            ldsm4(bh0, bh1, bh2, bh3, bHH + ko);
            ldsm4(bl0, bl1, bl2, bl3, bHL + ko);
            mma16816(acc1, awh, bh0, bh2);
            mma16816(acc2, awl, bh0, bh2);
            mma16816(acc3, awh, bl0, bl2);
        }
        float acc[4];
#pragma unroll
        for (int q = 0; q < 4; q++) acc[q] = (acc1[q] + acc2[q]) + acc3[q];

        // ---- epilogue: gates = acc + xg -> g_sm[b][c]
        g_sm[bA  * 132 + c_row]     = acc[0] + x00;
        g_sm[bB_ * 132 + c_row]     = acc[1] + x01;
        g_sm[bA  * 132 + c_row + 8] = acc[2] + x10;
        g_sm[bB_ * 132 + c_row + 8] = acc[3] + x11;
        __syncthreads();

        // ---- LSTM cell update: thread -> (ub, uj)
        {
            const float* gp = g_sm + ub * 132 + uj;
            const float gi = gp[0], gf = gp[32], gg2 = gp[64], go = gp[96];
            const float cc = sigf(gf) * c_sm[tid] + sigf(gi) * tanhf_(gg2);
            c_sm[tid] = cc;
            const float hh = sigf(go) * tanhf_(cc);

            g_hbuf[t & 1][dir][(size_t)(b0 + ub) * Hn + j0 + uj] = hh;

            const int opos = dir ? ((Tn - 1 - t + len_s[ub]) & (Tn - 1)) : t;
            out[((size_t)(b0 + ub) * Tn + opos) * (2 * Hn) + dir * Hn + j0 + uj] = hh;
        }
        __syncthreads();
        if (tid == 0) {
            const unsigned nv = (unsigned)(t + 1);
            asm volatile("st.release.gpu.u32 [%0], %1;" ::"l"(myflag), "r"(nv) : "memory");
        }
    }
}

// ---------------- launch -----------------------------------------------------------
extern "C" void kernel_launch(void* const* d_in, const int* in_sizes, int n_in,
                              void* d_out, int out_size) {
    (void)in_sizes; (void)n_in; (void)out_size;
    const float* inputs   = (const float*)d_in[0];
    const float* pads     = (const float*)d_in[1];
    const float* bn_scale = (const float*)d_in[2];
    const float* bn_bias  = (const float*)d_in[3];
    const float* bn_mean  = (const float*)d_in[4];
    const float* bn_var   = (const float*)d_in[5];
    const float* Wx_f     = (const float*)d_in[6];
    const float* Wh_f     = (const float*)d_in[7];
    const float* b_f      = (const float*)d_in[8];
    const float* Wx_b     = (const float*)d_in[9];
    const float* Wh_b     = (const float*)d_in[10];
    const float* b_b      = (const float*)d_in[11];
    float* out = (float*)d_out;

    static bool inited = false;
    if (!inited) {
        cudaFuncSetAttribute(gemm_mma_kernel,
                             cudaFuncAttributeMaxDynamicSharedMemorySize, GSMEM);
        cudaFuncSetAttribute(recurrence_kernel,
                             cudaFuncAttributeMaxDynamicSharedMemorySize, REC_SMEM);
        inited = true;
    }

    init_kernel<<<1, 128>>>();
    lengths_kernel<<<Bn, 256>>>(pads);
    bn_split_kernel<<<Bn * Tn, 128>>>(inputs, pads, bn_scale, bn_bias, bn_mean, bn_var);
    wprep_kernel<<<NTOT, 128>>>(Wx_f, Wx_b, b_f, b_b);
    gemm_mma_kernel<<<dim3(16, 512), 256, GSMEM>>>();
    recurrence_kernel<<<128, 256, REC_SMEM>>>(Wh_f, Wh_b, out);
}

// round 16
// speedup vs baseline: 1.0125x; 1.0125x over previous
#include <cuda_runtime.h>
#include <cuda_bf16.h>
#include <cstdint>
#include <cstddef>

#define Bn   64
#define Tn   1024
#define Dn   512
#define Hn   256
#define Gn   1024     /* 4*H */
#define NTOT 2048     /* both directions */
#define Mrows (Bn * Tn)
#define EPSC 0.001f

// ---------------- scratch (static device globals; allocation-free) ----------------
__device__ float          g_xg[(size_t)Bn * Tn * NTOT];   // 512 MB  xg for both dirs
__device__ __nv_bfloat16  g_ahi[(size_t)Mrows * Dn];      // 64 MB
__device__ __nv_bfloat16  g_alo[(size_t)Mrows * Dn];      // 64 MB
__device__ __nv_bfloat16  g_wthi[(size_t)NTOT * Dn];      // 2 MB  W^T hi  [n][k]
__device__ __nv_bfloat16  g_wtlo[(size_t)NTOT * Dn];      // 2 MB  W^T lo
__device__ float          g_bias2[NTOT];
__device__ uint32_t       g_hbuf2[2][2][Bn * Hn];         // packed (bf16 hi, bf16 lo)
__device__ int            g_len[Bn];
__device__ unsigned       g_flags[128];                   // [dir*64 + bs*8 + hs]

__device__ __forceinline__ float sigf(float x)  { return 1.0f / (1.0f + __expf(-x)); }
__device__ __forceinline__ float tanhf_(float x){ return 2.0f / (1.0f + __expf(-2.0f * x)) - 1.0f; }

__device__ __forceinline__ uint32_t smem_u32(const void* p) {
    uint32_t a;
    asm("{ .reg .u64 t; cvta.to.shared.u64 t, %1; cvt.u32.u64 %0, t; }" : "=r"(a) : "l"(p));
    return a;
}
__device__ __forceinline__ void cp16(uint32_t dst, const void* src) {
    asm volatile("cp.async.cg.shared.global [%0], [%1], 16;" :: "r"(dst), "l"(src));
}
#define CP_COMMIT() asm volatile("cp.async.commit_group;" ::: "memory")
#define CP_WAIT2()  asm volatile("cp.async.wait_group 2;" ::: "memory")
#define CP_WAIT1()  asm volatile("cp.async.wait_group 1;" ::: "memory")
#define CP_WAIT0()  asm volatile("cp.async.wait_group 0;" ::: "memory")

__device__ __forceinline__ void ldsm4(uint32_t& r0, uint32_t& r1, uint32_t& r2, uint32_t& r3,
                                      uint32_t addr) {
    asm volatile("ldmatrix.sync.aligned.m8n8.x4.shared.b16 {%0,%1,%2,%3}, [%4];"
                 : "=r"(r0), "=r"(r1), "=r"(r2), "=r"(r3) : "r"(addr));
}
__device__ __forceinline__ void mma16816(float* c, const uint32_t* a, uint32_t b0, uint32_t b1) {
    asm volatile("mma.sync.aligned.m16n8k16.row.col.f32.bf16.bf16.f32 "
                 "{%0,%1,%2,%3}, {%4,%5,%6,%7}, {%8,%9}, {%0,%1,%2,%3};"
                 : "+f"(c[0]), "+f"(c[1]), "+f"(c[2]), "+f"(c[3])
                 : "r"(a[0]), "r"(a[1]), "r"(a[2]), "r"(a[3]), "r"(b0), "r"(b1));
}
__device__ __forceinline__ uint32_t pack_bf16(float x, float y) {
    __nv_bfloat162 v = {__float2bfloat16(x), __float2bfloat16(y)};
    return *reinterpret_cast<uint32_t*>(&v);
}

// ---------------- init: zero the step-barrier flags (runs every graph replay) ------
__global__ void init_kernel() {
    if (threadIdx.x < 128) g_flags[threadIdx.x] = 0u;
}

// ---------------- lengths ----------------------------------------------------------
__global__ void lengths_kernel(const float* __restrict__ pads) {
    __shared__ float red[256];
    const int b = blockIdx.x;
    float s = 0.f;
    for (int t = threadIdx.x; t < Tn; t += 256) s += pads[b * Tn + t];
    red[threadIdx.x] = s;
    __syncthreads();
    for (int o = 128; o > 0; o >>= 1) {
        if (threadIdx.x < o) red[threadIdx.x] += red[threadIdx.x + o];
        __syncthreads();
    }
    if (threadIdx.x == 0) g_len[b] = Tn - (int)(red[0] + 0.5f);
}

// ---------------- BN + mask + bf16 hi/lo split -------------------------------------
__global__ void bn_split_kernel(const float* __restrict__ in, const float* __restrict__ pads,
                                const float* __restrict__ scale, const float* __restrict__ bias,
                                const float* __restrict__ mean, const float* __restrict__ var) {
    const int row = blockIdx.x;
    const int d   = threadIdx.x * 4;
    const float keep = 1.0f - pads[row];
    float4 v  = *(const float4*)(in + (size_t)row * Dn + d);
    float4 sc = *(const float4*)(scale + d);
    float4 bi = *(const float4*)(bias + d);
    float4 mu = *(const float4*)(mean + d);
    float4 va = *(const float4*)(var + d);
    float o[4];
    o[0] = ((v.x - mu.x) * ((1.0f + sc.x) * rsqrtf(va.x + EPSC)) + bi.x) * keep;
    o[1] = ((v.y - mu.y) * ((1.0f + sc.y) * rsqrtf(va.y + EPSC)) + bi.y) * keep;
    o[2] = ((v.z - mu.z) * ((1.0f + sc.z) * rsqrtf(va.z + EPSC)) + bi.z) * keep;
    o[3] = ((v.w - mu.w) * ((1.0f + sc.w) * rsqrtf(va.w + EPSC)) + bi.w) * keep;
    __nv_bfloat16 hi[4], lo[4];
#pragma unroll
    for (int q = 0; q < 4; q++) {
        hi[q] = __float2bfloat16(o[q]);
        lo[q] = __float2bfloat16(o[q] - __bfloat162float(hi[q]));
    }
    *(__nv_bfloat162*)(g_ahi + (size_t)row * Dn + d)     = {hi[0], hi[1]};
    *(__nv_bfloat162*)(g_ahi + (size_t)row * Dn + d + 2) = {hi[2], hi[3]};
    *(__nv_bfloat162*)(g_alo + (size_t)row * Dn + d)     = {lo[0], lo[1]};
    *(__nv_bfloat162*)(g_alo + (size_t)row * Dn + d + 2) = {lo[2], lo[3]};
}

// ---------------- W transpose + split + bias concat --------------------------------
__global__ void wprep_kernel(const float* __restrict__ Wxf, const float* __restrict__ Wxb,
                             const float* __restrict__ bf, const float* __restrict__ bb) {
    const int n = blockIdx.x;                 // 0..2047
    const float* W = (n < Gn) ? Wxf : Wxb;
    const int nl = n & (Gn - 1);
    for (int k = threadIdx.x; k < Dn; k += 128) {
        float v = W[(size_t)k * Gn + nl];
        __nv_bfloat16 h = __float2bfloat16(v);
        g_wthi[(size_t)n * Dn + k] = h;
        g_wtlo[(size_t)n * Dn + k] = __float2bfloat16(v - __bfloat162float(h));
    }
    if (threadIdx.x == 0) g_bias2[n] = (n < Gn) ? bf[nl] : bb[nl];
}

// ---------------- mma.sync GEMM, pad-row skip, 3-stage cp.async pipeline -----------
#define GCHUNKS 24
#define GSTAGE 32768
#define GSMEM  (3 * GSTAGE)

__global__ void __launch_bounds__(256, 2) gemm_mma_kernel() {
    const int n0 = blockIdx.x * 128;
    const int m0 = blockIdx.y * 128;

    {   // pad-block skip: entire block is padding -> xg never read, exit
        const int b  = m0 >> 10;
        const int t0 = m0 & (Tn - 1);
        if (t0 >= g_len[b]) return;
    }

    extern __shared__ __align__(1024) char sm[];
    const uint32_t smb = smem_u32(sm);
    const int tid  = threadIdx.x;
    const int wid  = tid >> 5, lane = tid & 31;
    const int wm   = wid & 3;
    const int wn   = wid >> 2;

    uint32_t sdstA[4];
    int arow[4];
#pragma unroll
    for (int j = 0; j < 4; j++) {
        const int item = tid + j * 256;
        const int row = item >> 3, ci = item & 7;
        arow[j] = row;
        sdstA[j] = row * 128 + ((ci * 16) ^ ((row & 7) << 4));
    }

    auto load_chunk = [&](int c, int s) {
        const int r  = c >> 3;
        const int kp = (c & 7) * 64;
        const __nv_bfloat16* Asrc = (r == 1) ? g_alo : g_ahi;
        const __nv_bfloat16* Bsrc = (r == 2) ? g_wtlo : g_wthi;
        const uint32_t aB = smb + s * GSTAGE;
        const uint32_t bB = aB + 16384;
#pragma unroll
        for (int j = 0; j < 4; j++) {
            const int item = tid + j * 256;
            const int ci = item & 7;
            cp16(aB + sdstA[j], Asrc + (size_t)(m0 + arow[j]) * Dn + kp + ci * 8);
        }
#pragma unroll
        for (int j = 0; j < 4; j++) {
            const int item = tid + j * 256;
            const int ci = item & 7;
            cp16(bB + sdstA[j], Bsrc + (size_t)(n0 + arow[j]) * Dn + kp + ci * 8);
        }
    };

    uint32_t aRel[2], aSx[2];
#pragma unroll
    for (int f = 0; f < 2; f++) {
        const int row = wm * 32 + f * 16 + (lane & 15);
        aRel[f] = row * 128;
        aSx[f]  = (row & 7) << 4;
    }
    uint32_t bRel[4], bSx[4];
#pragma unroll
    for (int q = 0; q < 4; q++) {
        const int row = wn * 64 + q * 16 + (lane & 15);
        bRel[q] = row * 128;
        bSx[q]  = (row & 7) << 4;
    }
    const uint32_t halfOff = (lane >> 4) * 16;

    float acc[2][8][4];
#pragma unroll
    for (int i = 0; i < 2; i++)
#pragma unroll
        for (int j = 0; j < 8; j++)
#pragma unroll
            for (int q = 0; q < 4; q++) acc[i][j][q] = 0.f;

    load_chunk(0, 0); CP_COMMIT();
    load_chunk(1, 1); CP_COMMIT();
    load_chunk(2, 2); CP_COMMIT();

    for (int i = 0; i < GCHUNKS; i++) {
        const int buf = i % 3;
        if (i < GCHUNKS - 2)      { CP_WAIT2(); }
        else if (i == GCHUNKS - 2){ CP_WAIT1(); }
        else                      { CP_WAIT0(); }
        __syncthreads();

        const uint32_t aB = smb + buf * GSTAGE;
        const uint32_t bB = aB + 16384;
#pragma unroll
        for (int k16 = 0; k16 < 4; k16++) {
            const uint32_t kb = k16 * 32 + halfOff;
            uint32_t af[2][4];
#pragma unroll
            for (int f = 0; f < 2; f++)
                ldsm4(af[f][0], af[f][1], af[f][2], af[f][3], aB + aRel[f] + (kb ^ aSx[f]));
#pragma unroll
            for (int q = 0; q < 4; q++) {
                uint32_t r0, r1, r2, r3;
                ldsm4(r0, r1, r2, r3, bB + bRel[q] + (kb ^ bSx[q]));
#pragma unroll
                for (int f = 0; f < 2; f++) {
                    mma16816(acc[f][2 * q + 0], af[f], r0, r2);
                    mma16816(acc[f][2 * q + 1], af[f], r1, r3);
                }
            }
        }
        __syncthreads();
        if (i + 3 < GCHUNKS) { load_chunk(i + 3, buf); CP_COMMIT(); }
    }

#pragma unroll
    for (int f = 0; f < 2; f++) {
        const int r0 = m0 + wm * 32 + f * 16 + (lane >> 2);
#pragma unroll
        for (int nf = 0; nf < 8; nf++) {
            const int col = n0 + wn * 64 + nf * 8 + (lane & 3) * 2;
            const float2 bv = *(const float2*)(g_bias2 + col);
            float2 o0 = {acc[f][nf][0] + bv.x, acc[f][nf][1] + bv.y};
            float2 o1 = {acc[f][nf][2] + bv.x, acc[f][nf][3] + bv.y};
            *(float2*)(g_xg + (size_t)r0 * NTOT + col)       = o0;
            *(float2*)(g_xg + (size_t)(r0 + 8) * NTOT + col) = o1;
        }
    }
}

// ---------------- Recurrence: tensor-core dot, packed-h exchange -------------------
// gates[128c][8b] = Wslice[c][k] @ h[b][k]^T via mma m16n8k16 (A=W m=128, B=h n=8).
// Producer packs (bf16 hi, bf16 lo) into one u32; consumer deinterleaves with PRMT.
// out[] stores moved after the flag release (off the inter-CTA critical path).
#define RSTR    264                       /* bf16 elems per smem row (528 B) */
#define OFF_WHH 0
#define OFF_WHL 67584                     /* 128*528 */
#define OFF_HHH 135168
#define OFF_HHL 143616                    /* +16*528 */
#define OFF_G   152064
#define OFF_C   156288                    /* +8*132*4 */
#define OFF_LEN 157312                    /* +256*4 */
#define REC_SMEM 157376

__global__ void __launch_bounds__(256, 1) recurrence_kernel(const float* __restrict__ Whf,
                                                            const float* __restrict__ Whb,
                                                            float* __restrict__ out) {
    extern __shared__ __align__(16) char smr[];
    const uint32_t smb = smem_u32(smr);
    __nv_bfloat16* Whh = (__nv_bfloat16*)(smr + OFF_WHH);
    __nv_bfloat16* Whl = (__nv_bfloat16*)(smr + OFF_WHL);
    float* g_sm  = (float*)(smr + OFF_G);     // [8][132]
    float* c_sm  = (float*)(smr + OFF_C);     // [256]
    int*   len_s = (int*)(smr + OFF_LEN);     // [8]

    const int tid = threadIdx.x;
    const int bx  = blockIdx.x;
    const int dir = bx >> 6;
    const int hs  = bx & 7;
    const int bs  = (bx >> 3) & 7;
    const int j0  = hs * 32;
    const int b0  = bs * 8;
    const float* Wh = dir ? Whb : Whf;

    // ---- init: W slice hi/lo into [c][k] layout (row = local col c = gate*32+jj)
    for (int idx = tid; idx < 32768; idx += 256) {
        const int n = idx & 127, k = idx >> 7;
        const int gate = n >> 5, jj = n & 31;
        const float v = Wh[(size_t)k * Gn + gate * Hn + j0 + jj];
        const __nv_bfloat16 h = __float2bfloat16(v);
        Whh[n * RSTR + k] = h;
        Whl[n * RSTR + k] = __float2bfloat16(v - __bfloat162float(h));
    }
    // zero both h tiles fully (incl. pad rows 8..15)
    for (int idx = tid; idx < (2 * 16 * RSTR * 2) / 4; idx += 256)
        ((uint32_t*)(smr + OFF_HHH))[idx] = 0;
    if (tid < 8) len_s[tid] = g_len[b0 + tid];
    c_sm[tid] = 0.f;
    __syncthreads();

    const int wid = tid >> 5, lane = tid & 31;
    // ldsm base addresses (k-dependent ks*32 added per step)
    const uint32_t aoff = (uint32_t)((wid * 16 + (lane & 15)) * 528 + (lane >> 4) * 16);
    const uint32_t aHH = smb + OFF_WHH + aoff;
    const uint32_t aHL = smb + OFF_WHL + aoff;
    const uint32_t boff = (uint32_t)((lane & 15) * 528 + (lane >> 4) * 16);
    const uint32_t bHH = smb + OFF_HHH + boff;
    const uint32_t bHL = smb + OFF_HHL + boff;

    // epilogue / xg mapping
    const int c_row = wid * 16 + (lane >> 2);            // local col, +8 sibling
    const int bA = (lane & 3) * 2, bB_ = bA + 1;         // two batches
    const int gcol0 = (c_row >> 5) * Hn + j0 + (c_row & 31);
    const int gcol1 = gcol0 + 8;
    const float* xg_dir = g_xg + dir * Gn;
    const float bias0 = g_bias2[dir * Gn + gcol0];       // pad-row substitute (exact)
    const float bias1 = g_bias2[dir * Gn + gcol1];
    const int lenA = len_s[bA], lenB = len_s[bB_];

    // conversion mapping
    const int cb = tid >> 5, ck = tid & 31;              // batch, k-octet
    const uint32_t cdstH = (uint32_t)(cb * 528 + ck * 16);

    // cell mapping
    const int ub = tid >> 5, uj = tid & 31;
    const int lenU = len_s[ub];

    unsigned* myflag = &g_flags[dir * 64 + bs * 8 + hs];

    for (int t = 0; t < Tn; t++) {
        // ---- xg for this step: valid rows from memory, pad rows = bias (exact)
        const int rA = dir ? ((Tn - 1 - t + lenA) & (Tn - 1)) : t;
        const int rB = dir ? ((Tn - 1 - t + lenB) & (Tn - 1)) : t;
        const bool vA = rA < lenA, vB = rB < lenB;
        const float x00 = vA ? __ldg(xg_dir + ((size_t)(b0 + bA)  * Tn + rA) * NTOT + gcol0) : bias0;
        const float x01 = vB ? __ldg(xg_dir + ((size_t)(b0 + bB_) * Tn + rB) * NTOT + gcol0) : bias0;
        const float x10 = vA ? __ldg(xg_dir + ((size_t)(b0 + bA)  * Tn + rA) * NTOT + gcol1) : bias1;
        const float x11 = vB ? __ldg(xg_dir + ((size_t)(b0 + bB_) * Tn + rB) * NTOT + gcol1) : bias1;

        if (t > 0) {
            if (tid < 8) {
                const unsigned* fp = &g_flags[dir * 64 + bs * 8 + tid];
                unsigned v;
                do {
                    asm volatile("ld.acquire.gpu.u32 %0, [%1];" : "=r"(v) : "l"(fp) : "memory");
                } while (v < (unsigned)t);
            }
            __syncthreads();
            // packed h -> deinterleave into hi/lo tiles (rows 0..7) via PRMT
            const uint32_t* hg = &g_hbuf2[(t + 1) & 1][dir][0];
            const uint4 q0 = __ldcg((const uint4*)(hg + (size_t)(b0 + cb) * Hn + ck * 8));
            const uint4 q1 = __ldcg((const uint4*)(hg + (size_t)(b0 + cb) * Hn + ck * 8 + 4));
            uint4 hi, lo;
            hi.x = __byte_perm(q0.x, q0.y, 0x5410); lo.x = __byte_perm(q0.x, q0.y, 0x7632);
            hi.y = __byte_perm(q0.z, q0.w, 0x5410); lo.y = __byte_perm(q0.z, q0.w, 0x7632);
            hi.z = __byte_perm(q1.x, q1.y, 0x5410); lo.z = __byte_perm(q1.x, q1.y, 0x7632);
            hi.w = __byte_perm(q1.z, q1.w, 0x5410); lo.w = __byte_perm(q1.z, q1.w, 0x7632);
            *(uint4*)(smr + OFF_HHH + cdstH) = hi;
            *(uint4*)(smr + OFF_HHL + cdstH) = lo;
            __syncthreads();
        }

        // ---- tensor dot: acc[c_row/(+8)][bA/bB_]
        float acc[4] = {0.f, 0.f, 0.f, 0.f};
#pragma unroll
        for (int ks = 0; ks < 16; ks++) {
            const uint32_t ko = ks * 32;
            uint32_t awh[4], awl[4], bh0, bh1, bh2, bh3, bl0, bl1, bl2, bl3;
            ldsm4(awh[0], awh[1], awh[2], awh[3], aHH + ko);
            ldsm4(awl[0], awl[1], awl[2], awl[3], aHL + ko);
            ldsm4(bh0, bh1, bh2, bh3, bHH + ko);
            ldsm4(bl0, bl1, bl2, bl3, bHL + ko);
            mma16816(acc, awh, bh0, bh2);
            mma16816(acc, awl, bh0, bh2);
            mma16816(acc, awh, bl0, bl2);
        }

        // ---- epilogue: gates = acc + xg -> g_sm[b][c]
        g_sm[bA  * 132 + c_row]     = acc[0] + x00;
        g_sm[bB_ * 132 + c_row]     = acc[1] + x01;
        g_sm[bA  * 132 + c_row + 8] = acc[2] + x10;
        g_sm[bB_ * 132 + c_row + 8] = acc[3] + x11;
        __syncthreads();

        // ---- LSTM cell update: thread -> (ub, uj); h stored packed (hi, lo)
        float hh;
        {
            const float* gp = g_sm + ub * 132 + uj;
            const float gi = gp[0], gf = gp[32], gg2 = gp[64], go = gp[96];
            const float cc = sigf(gf) * c_sm[tid] + sigf(gi) * tanhf_(gg2);
            c_sm[tid] = cc;
            hh = sigf(go) * tanhf_(cc);
            const float hiV = __bfloat162float(__float2bfloat16(hh));
            g_hbuf2[t & 1][dir][(size_t)(b0 + ub) * Hn + j0 + uj] = pack_bf16(hh, hh - hiV);
        }
        __syncthreads();
        if (tid == 0) {
            const unsigned nv = (unsigned)(t + 1);
            asm volatile("st.release.gpu.u32 [%0], %1;" ::"l"(myflag), "r"(nv) : "memory");
        }
        // out store after release — off the inter-CTA critical path
        {
            const int opos = dir ? ((Tn - 1 - t + lenU) & (Tn - 1)) : t;
            out[((size_t)(b0 + ub) * Tn + opos) * (2 * Hn) + dir * Hn + j0 + uj] = hh;
        }
    }
}

// ---------------- launch -----------------------------------------------------------
extern "C" void kernel_launch(void* const* d_in, const int* in_sizes, int n_in,
                              void* d_out, int out_size) {
    (void)in_sizes; (void)n_in; (void)out_size;
    const float* inputs   = (const float*)d_in[0];
    const float* pads     = (const float*)d_in[1];
    const float* bn_scale = (const float*)d_in[2];
    const float* bn_bias  = (const float*)d_in[3];
    const float* bn_mean  = (const float*)d_in[4];
    const float* bn_var   = (const float*)d_in[5];
    const float* Wx_f     = (const float*)d_in[6];
    const float* Wh_f     = (const float*)d_in[7];
    const float* b_f      = (const float*)d_in[8];
    const float* Wx_b     = (const float*)d_in[9];
    const float* Wh_b     = (const float*)d_in[10];
    const float* b_b      = (const float*)d_in[11];
    float* out = (float*)d_out;

    static bool inited = false;
    if (!inited) {
        cudaFuncSetAttribute(gemm_mma_kernel,
                             cudaFuncAttributeMaxDynamicSharedMemorySize, GSMEM);
        cudaFuncSetAttribute(recurrence_kernel,
                             cudaFuncAttributeMaxDynamicSharedMemorySize, REC_SMEM);
        inited = true;
    }

    init_kernel<<<1, 128>>>();
    lengths_kernel<<<Bn, 256>>>(pads);
    bn_split_kernel<<<Bn * Tn, 128>>>(inputs, pads, bn_scale, bn_bias, bn_mean, bn_var);
    wprep_kernel<<<NTOT, 128>>>(Wx_f, Wx_b, b_f, b_b);
    gemm_mma_kernel<<<dim3(16, 512), 256, GSMEM>>>();
    recurrence_kernel<<<128, 256, REC_SMEM>>>(Wh_f, Wh_b, out);
}